// round 4
// baseline (speedup 1.0000x reference)
#include <cuda_runtime.h>

#define N_NODES   10000
#define N_EDGES   640000
#define N_GRAPHS  64
#define F         128
#define NUM_CLASS 10

// ---------------- device scratch (no allocations allowed) ----------------
__device__ float g_h[N_NODES * F];      // h = x @ W  (pre-aggregation)
__device__ float g_x2[N_NODES * F];     // layer output (post relu)
__device__ int   g_deg[N_NODES];        // in-degree (on dst)
__device__ float g_dinv[N_NODES];       // rsqrt(deg+1)
__device__ int   g_rowstart[N_NODES];   // CSR row starts
__device__ int   g_fill[N_NODES];       // CSR fill cursors
__device__ int   g_col[N_EDGES];        // CSR column (src node) per edge slot
__device__ float g_sums[N_GRAPHS * F];  // pooled sums
__device__ int   g_cnt[N_GRAPHS];       // nodes per graph
__device__ int   g_any_odd;             // nonzero => odd 32-bit words nonzero => int32 data
__device__ int   g_is64;                // 1 if indices are int64, 0 if int32

// Index load helper: w points at a buffer of either int32 or int64 (LE) values.
__device__ __forceinline__ int load_idx(const int* __restrict__ w, int i, int is64) {
    return is64 ? w[2 * i] : w[i];
}

// ---------------- dtype detection ----------------
// Scan the first 2*N_EDGES 32-bit words of edge_index (safe under both dtypes).
// int64 (values < 2^31): every odd word is 0. int32: odd words are real indices.
__global__ void detect_kernel(const int* __restrict__ ei_w) {
    int i = blockIdx.x * blockDim.x + threadIdx.x;   // word pair index
    int acc = 0;
    // each thread checks 8 odd words
    for (int j = 0; j < 8; j++) {
        int w = i * 8 + j;                 // pair index
        int word = 2 * w + 1;              // odd word
        if (word < 2 * N_EDGES) acc |= ei_w[word];
    }
    if (acc) atomicOr(&g_any_odd, 1);
}

__global__ void set_flag_kernel() {
    g_is64 = (g_any_odd == 0) ? 1 : 0;
    g_any_odd = 0;  // reset for next (graph-replayed) run
}

// ---------------- zero ----------------
__global__ void zero_kernel() {
    int i = blockIdx.x * blockDim.x + threadIdx.x;
    if (i < N_NODES) { g_deg[i] = 0; g_fill[i] = 0; }
    if (i < N_GRAPHS * F) g_sums[i] = 0.0f;
    if (i < N_GRAPHS) g_cnt[i] = 0;
}

// ---------------- CSR build ----------------
__global__ void deg_kernel(const int* __restrict__ ei_w) {
    int e = blockIdx.x * blockDim.x + threadIdx.x;
    if (e < N_EDGES) {
        int is64 = g_is64;
        // dst element index = N_EDGES + e
        int d = load_idx(ei_w, N_EDGES + e, is64);
        if ((unsigned)d < N_NODES) atomicAdd(&g_deg[d], 1);
    }
}

__global__ void dinv_kernel() {
    int i = blockIdx.x * blockDim.x + threadIdx.x;
    if (i < N_NODES) g_dinv[i] = rsqrtf((float)g_deg[i] + 1.0f);
}

// single-block exclusive scan of g_deg -> g_rowstart (10000 elems, 1024 thr x 10)
__global__ void scan_kernel() {
    __shared__ int s[1024];
    const int C = 10;
    int tid = threadIdx.x;
    int base = tid * C;
    int local[C];
    int sum = 0;
#pragma unroll
    for (int j = 0; j < C; j++) {
        int idx = base + j;
        int v = (idx < N_NODES) ? g_deg[idx] : 0;
        local[j] = v;
        sum += v;
    }
    s[tid] = sum;
    __syncthreads();
    for (int off = 1; off < 1024; off <<= 1) {
        int v = (tid >= off) ? s[tid - off] : 0;
        __syncthreads();
        s[tid] += v;
        __syncthreads();
    }
    int run = s[tid] - sum;  // exclusive base for this chunk
#pragma unroll
    for (int j = 0; j < C; j++) {
        int idx = base + j;
        if (idx < N_NODES) {
            g_rowstart[idx] = run;
            run += local[j];
        }
    }
}

__global__ void fill_kernel(const int* __restrict__ ei_w) {
    int e = blockIdx.x * blockDim.x + threadIdx.x;
    if (e < N_EDGES) {
        int is64 = g_is64;
        int s = load_idx(ei_w, e, is64);
        int d = load_idx(ei_w, N_EDGES + e, is64);
        if ((unsigned)d < N_NODES && (unsigned)s < N_NODES) {
            int p = g_rowstart[d] + atomicAdd(&g_fill[d], 1);
            if ((unsigned)p < N_EDGES) g_col[p] = s;
        }
    }
}

// ---------------- dense transform ----------------
// g_h[node][f] = sum_k X[node][k] * W[k][f]; X chosen by from_x2 flag.
__global__ void gemm_kernel(const float* __restrict__ X,
                            const float* __restrict__ W,
                            int from_x2) {
    __shared__ float xs[F];
    int node = blockIdx.x;
    int t = threadIdx.x;
    xs[t] = from_x2 ? g_x2[node * F + t] : X[node * F + t];
    __syncthreads();
    float acc = 0.0f;
#pragma unroll 16
    for (int k = 0; k < F; k++) {
        acc = fmaf(xs[k], __ldg(&W[k * F + t]), acc);
    }
    g_h[node * F + t] = acc;
}

// ---------------- aggregate ----------------
// g_x2[i][f] = relu( dinv[i]*sum_e dinv[c]*g_h[c][f] + dinv[i]^2*g_h[i][f] + b[f] )
__global__ void gather_kernel(const float* __restrict__ b) {
    int i = blockIdx.x;
    int t = threadIdx.x;
    float di = g_dinv[i];
    int e   = g_rowstart[i];
    int end = e + g_deg[i];

    float acc0 = 0.0f, acc1 = 0.0f, acc2 = 0.0f, acc3 = 0.0f;
    for (; e + 4 <= end; e += 4) {
        int c0 = g_col[e + 0];
        int c1 = g_col[e + 1];
        int c2 = g_col[e + 2];
        int c3 = g_col[e + 3];
        float w0 = g_dinv[c0];
        float w1 = g_dinv[c1];
        float w2 = g_dinv[c2];
        float w3 = g_dinv[c3];
        acc0 = fmaf(w0, g_h[c0 * F + t], acc0);
        acc1 = fmaf(w1, g_h[c1 * F + t], acc1);
        acc2 = fmaf(w2, g_h[c2 * F + t], acc2);
        acc3 = fmaf(w3, g_h[c3 * F + t], acc3);
    }
    for (; e < end; e++) {
        int c = g_col[e];
        acc0 = fmaf(g_dinv[c], g_h[c * F + t], acc0);
    }
    float acc = (acc0 + acc1) + (acc2 + acc3);
    float v = di * acc + di * di * g_h[i * F + t] + b[t];
    g_x2[i * F + t] = fmaxf(v, 0.0f);
}

// ---------------- pool + head ----------------
__global__ void pool_kernel(const int* __restrict__ batch_w) {
    int i = blockIdx.x;
    int t = threadIdx.x;
    int g = load_idx(batch_w, i, g_is64);
    if ((unsigned)g < N_GRAPHS) {
        atomicAdd(&g_sums[g * F + t], g_x2[i * F + t]);
        if (t == 0) atomicAdd(&g_cnt[g], 1);
    }
}

__global__ void final_kernel(const float* __restrict__ Wlin,
                             const float* __restrict__ blin,
                             float* __restrict__ out) {
    __shared__ float row[F];
    int g = blockIdx.x;
    int t = threadIdx.x;
    float cnt = (float)g_cnt[g];
    cnt = fmaxf(cnt, 1.0f);
    row[t] = g_sums[g * F + t] / cnt;
    __syncthreads();
    if (t < NUM_CLASS) {
        float acc = blin[t];
#pragma unroll 16
        for (int k = 0; k < F; k++) {
            acc = fmaf(row[k], Wlin[k * NUM_CLASS + t], acc);
        }
        out[g * NUM_CLASS + t] = acc;
    }
}

// ---------------- launch: kernel launches ONLY ----------------

extern "C" void kernel_launch(void* const* d_in, const int* in_sizes, int n_in,
                              void* d_out, int out_size) {
    const float* x     = (const float*)d_in[0];
    const int*   ei_w  = (const int*)d_in[1];    // edge_index as 32-bit words
    const int*   bat_w = (const int*)d_in[2];    // batch as 32-bit words
    const float* W1    = (const float*)d_in[3];
    const float* b1    = (const float*)d_in[4];
    const float* W2    = (const float*)d_in[5];
    const float* b2    = (const float*)d_in[6];
    const float* Wlin  = (const float*)d_in[7];
    const float* blin  = (const float*)d_in[8];
    float* out = (float*)d_out;

    // dtype detection (int32 vs int64 indices)
    detect_kernel<<<(N_EDGES / 8 + 255) / 256, 256>>>(ei_w);
    set_flag_kernel<<<1, 1>>>();

    zero_kernel<<<(N_NODES + 255) / 256, 256>>>();

    deg_kernel<<<(N_EDGES + 255) / 256, 256>>>(ei_w);
    dinv_kernel<<<(N_NODES + 255) / 256, 256>>>();
    scan_kernel<<<1, 1024>>>();
    fill_kernel<<<(N_EDGES + 255) / 256, 256>>>(ei_w);

    gemm_kernel<<<N_NODES, F>>>(x, W1, 0);     // layer 1 transform
    gather_kernel<<<N_NODES, F>>>(b1);         // layer 1 aggregate+relu
    gemm_kernel<<<N_NODES, F>>>(x, W2, 1);     // layer 2 transform (reads g_x2)
    gather_kernel<<<N_NODES, F>>>(b2);         // layer 2 aggregate+relu
    pool_kernel<<<N_NODES, F>>>(bat_w);        // mean-pool sums
    final_kernel<<<N_GRAPHS, F>>>(Wlin, blin, out);
}

// round 7
// speedup vs baseline: 1.4682x; 1.4682x over previous
#include <cuda_runtime.h>

#define N_NODES   10000
#define N_EDGES   640000
#define N_GRAPHS  64
#define F         128
#define NUM_CLASS 10
#define MT        16          // gemm node tile

// ---------------- device scratch (no allocations allowed) ----------------
__device__ float g_h[N_NODES * F];      // h_scaled = (x @ W) * dinv[node]
__device__ float g_x2[N_NODES * F];     // layer output (post relu)
__device__ int   g_deg[N_NODES];        // in-degree (on dst)
__device__ float g_dinv[N_NODES];       // rsqrt(deg+1)
__device__ int   g_rowstart[N_NODES];   // CSR row starts
__device__ int   g_fill[N_NODES];       // CSR fill cursors
__device__ int   g_col[N_EDGES];        // CSR column (src node) per edge slot
__device__ float g_sums[N_GRAPHS * F];  // pooled sums
__device__ int   g_cnt[N_GRAPHS];       // nodes per graph
__device__ int   g_any_odd;             // nonzero => int32 data
__device__ int   g_is64;                // 1 if indices are int64, 0 if int32

// Index load helper: buffer holds either int32 or little-endian int64 values.
__device__ __forceinline__ int load_idx(const int* __restrict__ w, int i, int is64) {
    return is64 ? w[2 * i] : w[i];
}

// ---------------- setup: zero counters + sampled dtype detection ----------
// Sample 2048 odd 32-bit words, ALL with word index < 2*N_EDGES so the read
// is in-bounds whether the buffer holds int32 (2*N_EDGES words) or int64
// (4*N_EDGES words). If data is int64 (values < 2^31) every odd word is 0;
// for genuine int32 indices the chance all 2048 samples are 0 is negligible.
__global__ void setup_kernel(const int* __restrict__ ei_w) {
    int i = blockIdx.x * blockDim.x + threadIdx.x;
    if (i < N_NODES) { g_deg[i] = 0; g_fill[i] = 0; }
    if (i < N_GRAPHS * F) g_sums[i] = 0.0f;
    if (i < N_GRAPHS) g_cnt[i] = 0;
    if (i < 2048) {
        int k = i * 312;                 // pair index < N_EDGES (638,976 max)
        if (ei_w[2 * k + 1]) atomicOr(&g_any_odd, 1);
    }
}

__global__ void flag_kernel() {
    g_is64 = (g_any_odd == 0) ? 1 : 0;
    g_any_odd = 0;  // reset for replay
}

// ---------------- CSR build ----------------
__global__ void deg_kernel(const int* __restrict__ ei_w) {
    int base = (blockIdx.x * blockDim.x + threadIdx.x) * 4;
    int is64 = g_is64;
    int d0 = -1, d1 = -1, d2 = -1, d3 = -1;
    if (base + 0 < N_EDGES) d0 = load_idx(ei_w, N_EDGES + base + 0, is64);
    if (base + 1 < N_EDGES) d1 = load_idx(ei_w, N_EDGES + base + 1, is64);
    if (base + 2 < N_EDGES) d2 = load_idx(ei_w, N_EDGES + base + 2, is64);
    if (base + 3 < N_EDGES) d3 = load_idx(ei_w, N_EDGES + base + 3, is64);
    if ((unsigned)d0 < N_NODES) atomicAdd(&g_deg[d0], 1);
    if ((unsigned)d1 < N_NODES) atomicAdd(&g_deg[d1], 1);
    if ((unsigned)d2 < N_NODES) atomicAdd(&g_deg[d2], 1);
    if ((unsigned)d3 < N_NODES) atomicAdd(&g_deg[d3], 1);
}

// single-block exclusive scan of g_deg -> g_rowstart; also computes dinv.
__global__ void scan_kernel() {
    __shared__ int s[1024];
    const int C = 10;
    int tid = threadIdx.x;
    int base = tid * C;
    int local[C];
    int sum = 0;
#pragma unroll
    for (int j = 0; j < C; j++) {
        int idx = base + j;
        int v = (idx < N_NODES) ? g_deg[idx] : 0;
        local[j] = v;
        sum += v;
    }
    s[tid] = sum;
    __syncthreads();
    for (int off = 1; off < 1024; off <<= 1) {
        int v = (tid >= off) ? s[tid - off] : 0;
        __syncthreads();
        s[tid] += v;
        __syncthreads();
    }
    int run = s[tid] - sum;  // exclusive base for this chunk
#pragma unroll
    for (int j = 0; j < C; j++) {
        int idx = base + j;
        if (idx < N_NODES) {
            g_rowstart[idx] = run;
            run += local[j];
            g_dinv[idx] = rsqrtf((float)local[j] + 1.0f);
        }
    }
}

// fill CSR columns; also counts nodes per graph (first N_NODES threads).
__global__ void fill_kernel(const int* __restrict__ ei_w,
                            const int* __restrict__ batch_w) {
    int e = blockIdx.x * blockDim.x + threadIdx.x;
    int is64 = g_is64;
    if (e < N_EDGES) {
        int s = load_idx(ei_w, e, is64);
        int d = load_idx(ei_w, N_EDGES + e, is64);
        if ((unsigned)d < N_NODES && (unsigned)s < N_NODES) {
            int p = g_rowstart[d] + atomicAdd(&g_fill[d], 1);
            if ((unsigned)p < N_EDGES) g_col[p] = s;
        }
    }
    if (e < N_NODES) {
        int g = load_idx(batch_w, e, is64);
        if ((unsigned)g < N_GRAPHS) atomicAdd(&g_cnt[g], 1);
    }
}

// ---------------- dense transform (M-tiled) ----------------
// g_h[n][f] = dinv[n] * sum_k X[n][k] * W[k][f];  X selected by from_x2.
__global__ void gemm_kernel(const float* __restrict__ X,
                            const float* __restrict__ W,
                            int from_x2) {
    __shared__ float xs[MT * F];
    int t = threadIdx.x;               // feature index 0..127
    int node0 = blockIdx.x * MT;
#pragma unroll
    for (int r = 0; r < MT; r++) {
        int n = node0 + r;
        xs[r * F + t] = from_x2 ? g_x2[n * F + t] : X[n * F + t];
    }
    __syncthreads();
    float acc[MT];
#pragma unroll
    for (int m = 0; m < MT; m++) acc[m] = 0.0f;
#pragma unroll 4
    for (int k = 0; k < F; k++) {
        float w = __ldg(&W[k * F + t]);
#pragma unroll
        for (int m = 0; m < MT; m++) acc[m] = fmaf(xs[m * F + k], w, acc[m]);
    }
#pragma unroll
    for (int m = 0; m < MT; m++) {
        int n = node0 + m;
        g_h[n * F + t] = acc[m] * g_dinv[n];
    }
}

// ---------------- aggregate (+ optional fused mean-pool scatter) ----------
// g_h holds prescaled rows h_s[c] = dinv[c]*h[c]. Output:
//   v = relu( dinv[i] * ( h_s[i] + sum_c h_s[c] ) + b[f] )
// mode 0: write to g_x2.   mode 1: atomicAdd into g_sums[batch[i]].
__global__ void gather_kernel(const float* __restrict__ b, int mode,
                              const int* __restrict__ batch_w) {
    int i = blockIdx.x;
    int t = threadIdx.x;
    float di = g_dinv[i];
    int e   = g_rowstart[i];
    int end = e + g_deg[i];

    float a0 = g_h[i * F + t];   // self-loop term (already scaled by dinv[i])
    float a1 = 0.f, a2 = 0.f, a3 = 0.f, a4 = 0.f, a5 = 0.f, a6 = 0.f, a7 = 0.f;
    for (; e + 8 <= end; e += 8) {
        int c0 = g_col[e + 0];
        int c1 = g_col[e + 1];
        int c2 = g_col[e + 2];
        int c3 = g_col[e + 3];
        int c4 = g_col[e + 4];
        int c5 = g_col[e + 5];
        int c6 = g_col[e + 6];
        int c7 = g_col[e + 7];
        a0 += g_h[c0 * F + t];
        a1 += g_h[c1 * F + t];
        a2 += g_h[c2 * F + t];
        a3 += g_h[c3 * F + t];
        a4 += g_h[c4 * F + t];
        a5 += g_h[c5 * F + t];
        a6 += g_h[c6 * F + t];
        a7 += g_h[c7 * F + t];
    }
    for (; e < end; e++) {
        int c = g_col[e];
        a0 += g_h[c * F + t];
    }
    float acc = ((a0 + a1) + (a2 + a3)) + ((a4 + a5) + (a6 + a7));
    float v = fmaxf(fmaf(di, acc, b[t]), 0.0f);
    if (mode == 0) {
        g_x2[i * F + t] = v;
    } else {
        int g = load_idx(batch_w, i, g_is64);
        if ((unsigned)g < N_GRAPHS) atomicAdd(&g_sums[g * F + t], v);
    }
}

// ---------------- head ----------------
__global__ void final_kernel(const float* __restrict__ Wlin,
                             const float* __restrict__ blin,
                             float* __restrict__ out) {
    __shared__ float row[F];
    int g = blockIdx.x;
    int t = threadIdx.x;
    float cnt = (float)g_cnt[g];
    cnt = fmaxf(cnt, 1.0f);
    row[t] = g_sums[g * F + t] / cnt;
    __syncthreads();
    if (t < NUM_CLASS) {
        float acc = blin[t];
#pragma unroll 16
        for (int k = 0; k < F; k++) {
            acc = fmaf(row[k], Wlin[k * NUM_CLASS + t], acc);
        }
        out[g * NUM_CLASS + t] = acc;
    }
}

// ---------------- launch: kernel launches ONLY ----------------

extern "C" void kernel_launch(void* const* d_in, const int* in_sizes, int n_in,
                              void* d_out, int out_size) {
    const float* x     = (const float*)d_in[0];
    const int*   ei_w  = (const int*)d_in[1];    // edge_index as 32-bit words
    const int*   bat_w = (const int*)d_in[2];    // batch as 32-bit words
    const float* W1    = (const float*)d_in[3];
    const float* b1    = (const float*)d_in[4];
    const float* W2    = (const float*)d_in[5];
    const float* b2    = (const float*)d_in[6];
    const float* Wlin  = (const float*)d_in[7];
    const float* blin  = (const float*)d_in[8];
    float* out = (float*)d_out;

    setup_kernel<<<40, 256>>>(ei_w);                       // zero + detect
    flag_kernel<<<1, 1>>>();

    deg_kernel<<<(N_EDGES / 4 + 255) / 256, 256>>>(ei_w);
    scan_kernel<<<1, 1024>>>();                            // rowstart + dinv
    fill_kernel<<<(N_EDGES + 255) / 256, 256>>>(ei_w, bat_w);

    gemm_kernel<<<N_NODES / MT, F>>>(x, W1, 0);            // layer 1 transform
    gather_kernel<<<N_NODES, F>>>(b1, 0, bat_w);           // layer 1 agg+relu
    gemm_kernel<<<N_NODES / MT, F>>>(x, W2, 1);            // layer 2 transform
    gather_kernel<<<N_NODES, F>>>(b2, 1, bat_w);           // layer 2 agg+relu+pool
    final_kernel<<<N_GRAPHS, F>>>(Wlin, blin, out);
}

// round 10
// speedup vs baseline: 1.7082x; 1.1635x over previous
#include <cuda_runtime.h>
#include <cuda_fp16.h>

#define N_NODES   10000
#define N_EDGES   640000
#define N_GRAPHS  64
#define F         128
#define FH        64          // F/2 half2 per row
#define NUM_CLASS 10
#define MT        16          // gemm node tile

// ---------------- device scratch (no allocations allowed) ----------------
__device__ __half2 g_hh[N_NODES * FH];  // prescaled rows dinv[n]*(x@W)[n] as half2
__device__ float g_x2[N_NODES * F];     // layer output (post relu), fp32
__device__ int   g_deg[N_NODES];        // in-degree (on dst)
__device__ float g_dinv[N_NODES];       // rsqrt(deg+1)
__device__ int   g_rowstart[N_NODES];   // CSR row starts (arbitrary order)
__device__ int   g_fill[N_NODES];       // fill cursor; after fill = row end
__device__ int   g_col[N_EDGES];        // CSR column (src node) per edge slot
__device__ float g_sums[N_GRAPHS * F];  // pooled sums
__device__ int   g_cnt[N_GRAPHS];       // nodes per graph
__device__ int   g_total;               // global CSR cursor
__device__ int   g_any_odd;             // nonzero => int32 data
__device__ int   g_is64;                // 1 if indices are int64, 0 if int32

__device__ __forceinline__ int load_idx(const int* __restrict__ w, int i, int is64) {
    return is64 ? w[2 * i] : w[i];
}

// ---------------- setup: zero counters + sampled dtype detection ----------
// All sampled word indices < 2*N_EDGES: in-bounds for int32 AND int64 buffers.
__global__ void setup_kernel(const int* __restrict__ ei_w) {
    int i = blockIdx.x * blockDim.x + threadIdx.x;
    if (i < N_GRAPHS * F) g_sums[i] = 0.0f;
    if (i < N_GRAPHS) g_cnt[i] = 0;
    if (i == 0) g_total = 0;
    if (i < 2048) {
        int k = i * 312;                 // pair index < N_EDGES
        if (ei_w[2 * k + 1]) atomicOr(&g_any_odd, 1);
    }
    if (i < N_NODES) g_deg[i] = 0;
}

__global__ void flag_kernel() {
    g_is64 = (g_any_odd == 0) ? 1 : 0;
    g_any_odd = 0;  // reset for replay
}

// ---------------- CSR build ----------------
__global__ void deg_kernel(const int* __restrict__ ei_w) {
    int base = (blockIdx.x * blockDim.x + threadIdx.x) * 4;
    int is64 = g_is64;
    int d0 = -1, d1 = -1, d2 = -1, d3 = -1;
    if (base + 0 < N_EDGES) d0 = load_idx(ei_w, N_EDGES + base + 0, is64);
    if (base + 1 < N_EDGES) d1 = load_idx(ei_w, N_EDGES + base + 1, is64);
    if (base + 2 < N_EDGES) d2 = load_idx(ei_w, N_EDGES + base + 2, is64);
    if (base + 3 < N_EDGES) d3 = load_idx(ei_w, N_EDGES + base + 3, is64);
    if ((unsigned)d0 < N_NODES) atomicAdd(&g_deg[d0], 1);
    if ((unsigned)d1 < N_NODES) atomicAdd(&g_deg[d1], 1);
    if ((unsigned)d2 < N_NODES) atomicAdd(&g_deg[d2], 1);
    if ((unsigned)d3 < N_NODES) atomicAdd(&g_deg[d3], 1);
}

// Parallel CSR base assignment: row segments in arbitrary (block-granular)
// order. Block-local shfl scan + one global atomicAdd per block.
// Also: dinv and fill-cursor init.
__global__ void base_kernel() {
    int i = blockIdx.x * blockDim.x + threadIdx.x;
    int d = (i < N_NODES) ? g_deg[i] : 0;

    int lane = threadIdx.x & 31;
    int warp = threadIdx.x >> 5;

    // warp-inclusive scan of d
    int v = d;
#pragma unroll
    for (int off = 1; off < 32; off <<= 1) {
        int n = __shfl_up_sync(0xFFFFFFFFu, v, off);
        if (lane >= off) v += n;
    }

    __shared__ int wsum[8];
    __shared__ int woff[8];
    if (lane == 31) wsum[warp] = v;
    __syncthreads();
    if (threadIdx.x == 0) {
        int tot = 0;
#pragma unroll
        for (int w = 0; w < 8; w++) { int t = wsum[w]; wsum[w] = tot; tot += t; }
        int base = atomicAdd(&g_total, tot);
#pragma unroll
        for (int w = 0; w < 8; w++) woff[w] = base + wsum[w];
    }
    __syncthreads();

    if (i < N_NODES) {
        int rs = woff[warp] + (v - d);   // exclusive within block + block base
        g_rowstart[i] = rs;
        g_fill[i] = rs;
        g_dinv[i] = rsqrtf((float)d + 1.0f);
    }
}

// fill CSR columns; also counts nodes per graph (first N_NODES threads).
__global__ void fill_kernel(const int* __restrict__ ei_w,
                            const int* __restrict__ batch_w) {
    int e = blockIdx.x * blockDim.x + threadIdx.x;
    int is64 = g_is64;
    if (e < N_EDGES) {
        int s = load_idx(ei_w, e, is64);
        int d = load_idx(ei_w, N_EDGES + e, is64);
        if ((unsigned)d < N_NODES && (unsigned)s < N_NODES) {
            int p = atomicAdd(&g_fill[d], 1);
            if ((unsigned)p < N_EDGES) g_col[p] = s;
        }
    }
    if (e < N_NODES) {
        int g = load_idx(batch_w, e, is64);
        if ((unsigned)g < N_GRAPHS) atomicAdd(&g_cnt[g], 1);
    }
}

// ---------------- dense transform (M-tiled), fp16 output ----------------
// g_hh[n][f/2] = half2( dinv[n] * (X[n] @ W)[f] );  X selected by from_x2.
__global__ void gemm_kernel(const float* __restrict__ X,
                            const float* __restrict__ W,
                            int from_x2) {
    __shared__ float xs[MT * F];
    int t = threadIdx.x;               // feature index 0..127
    int node0 = blockIdx.x * MT;
#pragma unroll
    for (int r = 0; r < MT; r++) {
        int n = node0 + r;
        xs[r * F + t] = from_x2 ? g_x2[n * F + t] : X[n * F + t];
    }
    __syncthreads();
    float acc[MT];
#pragma unroll
    for (int m = 0; m < MT; m++) acc[m] = 0.0f;
#pragma unroll 4
    for (int k = 0; k < F; k++) {
        float w = __ldg(&W[k * F + t]);
#pragma unroll
        for (int m = 0; m < MT; m++) acc[m] = fmaf(xs[m * F + k], w, acc[m]);
    }
#pragma unroll
    for (int m = 0; m < MT; m++) {
        int n = node0 + m;
        float v = acc[m] * g_dinv[n];
        float other = __shfl_down_sync(0xFFFFFFFFu, v, 1);
        if ((t & 1) == 0) {
            g_hh[n * FH + (t >> 1)] = __floats2half2_rn(v, other);
        }
    }
}

// ---------------- aggregate (+ optional fused mean-pool scatter) ----------
// g_hh holds prescaled rows. v = relu( dinv[i]*(hh[i] + sum_c hh[c]) + b )
// 64 threads per block, one half2 (2 features) per thread; fp32 accumulation.
// mode 0: write g_x2 (float2). mode 1: atomicAdd into g_sums[batch[i]].
__global__ void gather_kernel(const float* __restrict__ b, int mode,
                              const int* __restrict__ batch_w) {
    int i = blockIdx.x;
    int t = threadIdx.x;               // 0..63
    float di = g_dinv[i];
    int e   = g_rowstart[i];
    int end = g_fill[i];               // rowstart + deg after fill

    float2 s = __half22float2(g_hh[i * FH + t]);   // self-loop term
    float a0x = s.x, a0y = s.y;
    float a1x = 0.f, a1y = 0.f, a2x = 0.f, a2y = 0.f, a3x = 0.f, a3y = 0.f;
    float a4x = 0.f, a4y = 0.f, a5x = 0.f, a5y = 0.f, a6x = 0.f, a6y = 0.f;
    float a7x = 0.f, a7y = 0.f;
    for (; e + 8 <= end; e += 8) {
        int c0 = g_col[e + 0];
        int c1 = g_col[e + 1];
        int c2 = g_col[e + 2];
        int c3 = g_col[e + 3];
        int c4 = g_col[e + 4];
        int c5 = g_col[e + 5];
        int c6 = g_col[e + 6];
        int c7 = g_col[e + 7];
        float2 f0 = __half22float2(g_hh[c0 * FH + t]);
        float2 f1 = __half22float2(g_hh[c1 * FH + t]);
        float2 f2 = __half22float2(g_hh[c2 * FH + t]);
        float2 f3 = __half22float2(g_hh[c3 * FH + t]);
        float2 f4 = __half22float2(g_hh[c4 * FH + t]);
        float2 f5 = __half22float2(g_hh[c5 * FH + t]);
        float2 f6 = __half22float2(g_hh[c6 * FH + t]);
        float2 f7 = __half22float2(g_hh[c7 * FH + t]);
        a0x += f0.x; a0y += f0.y;
        a1x += f1.x; a1y += f1.y;
        a2x += f2.x; a2y += f2.y;
        a3x += f3.x; a3y += f3.y;
        a4x += f4.x; a4y += f4.y;
        a5x += f5.x; a5y += f5.y;
        a6x += f6.x; a6y += f6.y;
        a7x += f7.x; a7y += f7.y;
    }
    for (; e < end; e++) {
        int c = g_col[e];
        float2 f = __half22float2(g_hh[c * FH + t]);
        a0x += f.x; a0y += f.y;
    }
    float ax = ((a0x + a1x) + (a2x + a3x)) + ((a4x + a5x) + (a6x + a7x));
    float ay = ((a0y + a1y) + (a2y + a3y)) + ((a4y + a5y) + (a6y + a7y));
    float vx = fmaxf(fmaf(di, ax, b[2 * t + 0]), 0.0f);
    float vy = fmaxf(fmaf(di, ay, b[2 * t + 1]), 0.0f);
    if (mode == 0) {
        *(float2*)&g_x2[i * F + 2 * t] = make_float2(vx, vy);
    } else {
        int g = load_idx(batch_w, i, g_is64);
        if ((unsigned)g < N_GRAPHS) {
            atomicAdd(&g_sums[g * F + 2 * t + 0], vx);
            atomicAdd(&g_sums[g * F + 2 * t + 1], vy);
        }
    }
}

// ---------------- head ----------------
__global__ void final_kernel(const float* __restrict__ Wlin,
                             const float* __restrict__ blin,
                             float* __restrict__ out) {
    __shared__ float row[F];
    int g = blockIdx.x;
    int t = threadIdx.x;
    float cnt = (float)g_cnt[g];
    cnt = fmaxf(cnt, 1.0f);
    row[t] = g_sums[g * F + t] / cnt;
    __syncthreads();
    if (t < NUM_CLASS) {
        float acc = blin[t];
#pragma unroll 16
        for (int k = 0; k < F; k++) {
            acc = fmaf(row[k], Wlin[k * NUM_CLASS + t], acc);
        }
        out[g * NUM_CLASS + t] = acc;
    }
}

// ---------------- launch: kernel launches ONLY ----------------

extern "C" void kernel_launch(void* const* d_in, const int* in_sizes, int n_in,
                              void* d_out, int out_size) {
    const float* x     = (const float*)d_in[0];
    const int*   ei_w  = (const int*)d_in[1];    // edge_index as 32-bit words
    const int*   bat_w = (const int*)d_in[2];    // batch as 32-bit words
    const float* W1    = (const float*)d_in[3];
    const float* b1    = (const float*)d_in[4];
    const float* W2    = (const float*)d_in[5];
    const float* b2    = (const float*)d_in[6];
    const float* Wlin  = (const float*)d_in[7];
    const float* blin  = (const float*)d_in[8];
    float* out = (float*)d_out;

    setup_kernel<<<40, 256>>>(ei_w);                       // zero + detect
    flag_kernel<<<1, 1>>>();

    deg_kernel<<<(N_EDGES / 4 + 255) / 256, 256>>>(ei_w);
    base_kernel<<<(N_NODES + 255) / 256, 256>>>();         // rowstart+dinv+cursors
    fill_kernel<<<(N_EDGES + 255) / 256, 256>>>(ei_w, bat_w);

    gemm_kernel<<<N_NODES / MT, F>>>(x, W1, 0);            // layer 1 transform
    gather_kernel<<<N_NODES, FH>>>(b1, 0, bat_w);          // layer 1 agg+relu
    gemm_kernel<<<N_NODES / MT, F>>>(x, W2, 1);            // layer 2 transform
    gather_kernel<<<N_NODES, FH>>>(b2, 1, bat_w);          // layer 2 agg+relu+pool
    final_kernel<<<N_GRAPHS, F>>>(Wlin, blin, out);
}